// round 16
// baseline (speedup 1.0000x reference)
#include <cuda_runtime.h>
#include <cuda_fp16.h>
#include <stdint.h>

// SkinningField R16: R15 + layer0 via m16n8k8 (zero-padded K dropped; 4 ldx4 +
// 16 k8-HMMA per half) + epilogue xyz/quat loads hoisted above the prob tree.

#define H    128
#define NB   55
#define TILE 512          // 16 warps x 32 points
#define NWARP 16
#define WSTR 136          // W1/W2/W3 row stride (fp16 elems)
#define W0STR 8           // W0 blob row stride (fp16): 16B rows
#define ESTR 65           // logit staging row stride (floats)

#define OFF_W1  0
#define OFF_W2  34816
#define OFF_W3  69632
#define OFF_W0H 87040                  // 128*8*2 = 2048 B
#define OFF_B1  (OFF_W0H + 2048)       // 89088
#define OFF_B2  (OFF_B1 + 512)
#define OFF_B3  (OFF_B2 + 512)
#define OFF_ES  (OFF_B3 + 256)         // 90368
#define OFF_TFS (OFF_ES + NWARP * 32 * ESTR * 4)   // 223488
#define SMEM_TOTAL (OFF_TFS + NB * 16 * 4)         // 227008

struct __align__(16) WBlob {
    __half w1[128 * WSTR];
    __half w2[128 * WSTR];
    __half w3[64 * WSTR];
    __half w0[128 * W0STR];   // [n][k]: k0..2 = W0 rows, k3 = b0, k4..7 = 0
};
__device__ WBlob g_wt;

// ---------------- helpers ----------------
__device__ __forceinline__ uint32_t smem_u32(const void* p) {
    uint32_t a;
    asm("{ .reg .u64 t; cvta.to.shared.u64 t, %1; cvt.u32.u64 %0, t; }" : "=r"(a) : "l"(p));
    return a;
}
__device__ __forceinline__ float sigf(float v) {
    return __fdividef(1.0f, 1.0f + __expf(-v));
}
__device__ __forceinline__ void sm3(float a, float b, float c, float& oa, float& ob, float& oc) {
    float m = fmaxf(a, fmaxf(b, c));
    float ea = __expf(a - m), eb = __expf(b - m), ec = __expf(c - m);
    float inv = __fdividef(1.0f, ea + eb + ec);
    oa = ea * inv; ob = eb * inv; oc = ec * inv;
}
__device__ __forceinline__ void sm5(float a, float b, float c, float d, float e,
                                    float& oa, float& ob, float& oc, float& od, float& oe) {
    float m = fmaxf(fmaxf(a, b), fmaxf(fmaxf(c, d), e));
    float ea = __expf(a - m), eb = __expf(b - m), ec = __expf(c - m),
          ed = __expf(d - m), ee = __expf(e - m);
    float inv = __fdividef(1.0f, ea + eb + ec + ed + ee);
    oa = ea * inv; ob = eb * inv; oc = ec * inv; od = ed * inv; oe = ee * inv;
}
__device__ __forceinline__ uint32_t pack_h2(float h0, float h1) {
    uint32_t w;
    asm("cvt.rn.f16x2.f32 %0, %1, %2;" : "=r"(w) : "f"(h1), "f"(h0));
    return w;
}
// exact-form softplus: ln2 * lg2(1 + 2^(x*log2e)); valid for |x| << 88
__device__ __forceinline__ float spf(float x) {
    float e, l;
    asm("ex2.approx.ftz.f32 %0, %1;" : "=f"(e) : "f"(x * 1.4426950408889634f));
    asm("lg2.approx.ftz.f32 %0, %1;" : "=f"(l) : "f"(1.0f + e));
    return 0.6931471805599453f * l;
}

__device__ __forceinline__ unsigned long long fma2(unsigned long long a,
                                                   unsigned long long b,
                                                   unsigned long long c) {
    unsigned long long r;
    asm("fma.rn.f32x2 %0, %1, %2, %3;" : "=l"(r) : "l"(a), "l"(b), "l"(c));
    return r;
}
__device__ __forceinline__ unsigned long long bcast2(float w) {
    unsigned long long r;
    asm("mov.b64 %0, {%1, %1};" : "=l"(r) : "f"(w));
    return r;
}
__device__ __forceinline__ void unpack2(unsigned long long v, float& lo, float& hi) {
    asm("mov.b64 {%0, %1}, %2;" : "=f"(lo), "=f"(hi) : "l"(v));
}

__device__ __forceinline__ void mma_f16(float& d0, float& d1, float& d2, float& d3,
                                        uint32_t a0, uint32_t a1, uint32_t a2, uint32_t a3,
                                        uint32_t b0, uint32_t b1) {
    asm volatile("mma.sync.aligned.m16n8k16.row.col.f32.f16.f16.f32 "
                 "{%0,%1,%2,%3}, {%4,%5,%6,%7}, {%8,%9}, {%0,%1,%2,%3};"
                 : "+f"(d0), "+f"(d1), "+f"(d2), "+f"(d3)
                 : "r"(a0), "r"(a1), "r"(a2), "r"(a3), "r"(b0), "r"(b1));
}
__device__ __forceinline__ void mma_f16_zc(float& d0, float& d1, float& d2, float& d3,
                                           uint32_t a0, uint32_t a1, uint32_t a2, uint32_t a3,
                                           uint32_t b0, uint32_t b1) {
    const float z = 0.0f;
    asm volatile("mma.sync.aligned.m16n8k16.row.col.f32.f16.f16.f32 "
                 "{%0,%1,%2,%3}, {%4,%5,%6,%7}, {%8,%9}, {%10,%11,%12,%13};"
                 : "=f"(d0), "=f"(d1), "=f"(d2), "=f"(d3)
                 : "r"(a0), "r"(a1), "r"(a2), "r"(a3), "r"(b0), "r"(b1),
                   "f"(z), "f"(z), "f"(z), "f"(z));
}
// k8 zero-C MMA: D = A(k8)*B(k8)
__device__ __forceinline__ void mma_f16_k8_zc(float& d0, float& d1, float& d2, float& d3,
                                              uint32_t a0, uint32_t a1, uint32_t b0) {
    const float z = 0.0f;
    asm volatile("mma.sync.aligned.m16n8k8.row.col.f32.f16.f16.f32 "
                 "{%0,%1,%2,%3}, {%4,%5}, {%6}, {%7,%8,%9,%10};"
                 : "=f"(d0), "=f"(d1), "=f"(d2), "=f"(d3)
                 : "r"(a0), "r"(a1), "r"(b0),
                   "f"(z), "f"(z), "f"(z), "f"(z));
}

__device__ __forceinline__ void ldx4s(uint32_t b[4], uint32_t base, int lane,
                                      int n0, int k0, int stride_elem) {
    int grp = lane >> 3, r = lane & 7;
    int row = n0 + r + ((grp >> 1) << 3);
    int col = k0 + ((grp & 1) << 3);
    uint32_t addr = base + (uint32_t)(row * stride_elem + col) * 2u;
    asm volatile("ldmatrix.sync.aligned.m8n8.x4.shared.b16 {%0,%1,%2,%3}, [%4];"
                 : "=r"(b[0]), "=r"(b[1]), "=r"(b[2]), "=r"(b[3]) : "r"(addr));
}
// 32-row x 8-col ldmatrix: rows n0..n0+31, one 16B row each -> 4 n8 k8 frags
__device__ __forceinline__ void ldx4_rows32(uint32_t b[4], uint32_t base, int lane, int n0) {
    uint32_t addr = base + (uint32_t)((n0 + lane) * W0STR) * 2u;
    asm volatile("ldmatrix.sync.aligned.m8n8.x4.shared.b16 {%0,%1,%2,%3}, [%4];"
                 : "=r"(b[0]), "=r"(b[1]), "=r"(b[2]), "=r"(b[3]) : "r"(addr));
}

template <int NC>
__device__ __forceinline__ void gemm_layer(float acc[][4], const uint32_t ahi[8][4],
                                           uint32_t wsm, int lane) {
    #pragma unroll
    for (int kk = 0; kk < 8; ++kk) {
        #pragma unroll
        for (int jj = 0; jj < NC / 2; ++jj) {
            uint32_t bh[4];
            ldx4s(bh, wsm, lane, 16 * jj, 16 * kk, WSTR);
            float* aL = acc[2 * jj];
            float* aR = acc[2 * jj + 1];
            if (kk == 0) {
                mma_f16_zc(aL[0], aL[1], aL[2], aL[3], ahi[kk][0], ahi[kk][1], ahi[kk][2], ahi[kk][3], bh[0], bh[1]);
                mma_f16_zc(aR[0], aR[1], aR[2], aR[3], ahi[kk][0], ahi[kk][1], ahi[kk][2], ahi[kk][3], bh[2], bh[3]);
            } else {
                mma_f16(aL[0], aL[1], aL[2], aL[3], ahi[kk][0], ahi[kk][1], ahi[kk][2], ahi[kk][3], bh[0], bh[1]);
                mma_f16(aR[0], aR[1], aR[2], aR[3], ahi[kk][0], ahi[kk][1], ahi[kk][2], ahi[kk][3], bh[2], bh[3]);
            }
        }
    }
}

__device__ __forceinline__ void act_pack(const float acc[][4], const float* bias_s,
                                         uint32_t ahi[8][4], int lane) {
    const int cbase = 2 * (lane & 3);
    #pragma unroll
    for (int j = 0; j < 16; ++j) {
        int c = 8 * j + cbase;
        float h0 = spf(acc[j][0] + bias_s[c]);
        float h1 = spf(acc[j][1] + bias_s[c + 1]);
        float h2 = spf(acc[j][2] + bias_s[c]);
        float h3 = spf(acc[j][3] + bias_s[c + 1]);
        int kk = j >> 1, half = (j & 1) << 1;
        ahi[kk][half]     = pack_h2(h0, h1);
        ahi[kk][half + 1] = pack_h2(h2, h3);
    }
}
__device__ __forceinline__ void act_pack0(const float acc[][4], uint32_t ahi[8][4]) {
    #pragma unroll
    for (int j = 0; j < 16; ++j) {
        float h0 = spf(acc[j][0]);
        float h1 = spf(acc[j][1]);
        float h2 = spf(acc[j][2]);
        float h3 = spf(acc[j][3]);
        int kk = j >> 1, half = (j & 1) << 1;
        ahi[kk][half]     = pack_h2(h0, h1);
        ahi[kk][half + 1] = pack_h2(h2, h3);
    }
}

// T-blend accumulate: tfs rows from SMEM as double2 (LDS.128 broadcast)
__device__ __forceinline__ void tacc(unsigned long long TP[8], const double2* tfs_d2,
                                     int b, float w) {
    unsigned long long wpk = bcast2(w);
    #pragma unroll
    for (int i = 0; i < 4; ++i) {
        double2 v = tfs_d2[b * 4 + i];
        TP[2 * i]     = fma2(wpk, *(unsigned long long*)&v.x, TP[2 * i]);
        TP[2 * i + 1] = fma2(wpk, *(unsigned long long*)&v.y, TP[2 * i + 1]);
    }
}

// ---------------- prep ----------------
__global__ void prep_kernel(const float* __restrict__ W0, const float* __restrict__ b0,
                            const float* __restrict__ W1, const float* __restrict__ W2,
                            const float* __restrict__ W3) {
    int tid = blockIdx.x * blockDim.x + threadIdx.x;
    int stride = gridDim.x * blockDim.x;
    for (int o = tid; o < 128 * WSTR; o += stride) {
        int n = o / WSTR, k = o % WSTR;
        float f1 = 0.f, f2 = 0.f;
        if (k < 128) { f1 = W1[k * 128 + n]; f2 = W2[k * 128 + n]; }
        g_wt.w1[o] = __float2half_rn(f1);
        g_wt.w2[o] = __float2half_rn(f2);
    }
    for (int o = tid; o < 64 * WSTR; o += stride) {
        int n = o / WSTR, k = o % WSTR;
        float f = (n < 59 && k < 128) ? W3[k * 59 + n] : 0.f;
        g_wt.w3[o] = __float2half_rn(f);
    }
    for (int o = tid; o < 128 * W0STR; o += stride) {
        int n = o / W0STR, k = o % W0STR;
        float f = 0.f;
        if (k < 3)       f = W0[k * 128 + n];
        else if (k == 3) f = b0[n];
        g_wt.w0[o] = __float2half_rn(f);
    }
}

// ---------------- main kernel ----------------
__global__ void __launch_bounds__(512, 1)
skin_mma_kernel(const float* __restrict__ xyz,  const float* __restrict__ quats,
                const float* __restrict__ tfs,  const float* __restrict__ aabb_min,
                const float* __restrict__ aabb_max,
                const float* __restrict__ b1, const float* __restrict__ b2,
                const float* __restrict__ b3,
                float* __restrict__ out, int Npts, int ntiles)
{
    extern __shared__ char smem[];
    const int tid  = threadIdx.x;
    const int wid  = tid >> 5;
    const int lane = tid & 31;

    {
        const uint4* src = (const uint4*)&g_wt;
        uint4* dst = (uint4*)smem;
        for (int i = tid; i < (int)(sizeof(WBlob) / 16); i += 512) dst[i] = src[i];
    }
    float* b1s  = (float*)(smem + OFF_B1);
    float* b2s  = (float*)(smem + OFF_B2);
    float* b3s  = (float*)(smem + OFF_B3);
    float* tfs_f = (float*)(smem + OFF_TFS);
    if (tid < H) { b1s[tid] = b1[tid]; b2s[tid] = b2[tid]; }
    if (tid < 64) b3s[tid] = (tid < 59) ? b3[tid] : 0.0f;
    for (int i = tid; i < NB * 16; i += 512) tfs_f[i] = tfs[i];
    __syncthreads();

    const uint32_t u_w1  = smem_u32(smem + OFF_W1);
    const uint32_t u_w2  = smem_u32(smem + OFF_W2);
    const uint32_t u_w3  = smem_u32(smem + OFF_W3);
    const uint32_t u_w0h = smem_u32(smem + OFF_W0H);
    float* es_w = (float*)(smem + OFF_ES) + wid * (32 * ESTR);
    const double2* tfs_d2 = (const double2*)(smem + OFF_TFS);

    const float amn0 = __ldg(aabb_min + 0), amn1 = __ldg(aabb_min + 1), amn2 = __ldg(aabb_min + 2);
    const float amx0 = __ldg(aabb_max + 0), amx1 = __ldg(aabb_max + 1), amx2 = __ldg(aabb_max + 2);
    const float sc0 = 2.0f / (amx0 - amn0), sc1 = 2.0f / (amx1 - amn1), sc2 = 2.0f / (amx2 - amn2);

    const int g = lane >> 2;
    const int cbase = 2 * (lane & 3);
    const int tsel = lane & 3;
    const int wpar = wid & 1;

    for (int t = blockIdx.x; t < ntiles; t += gridDim.x) {
        const int pbase_w = t * TILE + wid * 32;

        #pragma unroll
        for (int hh = 0; hh < 2; ++hh) {
            const int hf = hh ^ wpar;
            const int base16 = pbase_w + hf * 16;
            uint32_t ahi[8][4];
            float acc[16][4];

            // ---- layer 0 via m16n8k8: A = [xn0,xn1,xn2,1] (K=8, k4..7=0) ----
            {
                int pA = base16 + g;     if (pA >= Npts) pA = Npts - 1;
                int pB = base16 + g + 8; if (pB >= Npts) pB = Npts - 1;
                float xA0 = (xyz[(size_t)pA * 3 + 0] - amn0) * sc0 - 1.0f;
                float xA1 = (xyz[(size_t)pA * 3 + 1] - amn1) * sc1 - 1.0f;
                float xA2 = (xyz[(size_t)pA * 3 + 2] - amn2) * sc2 - 1.0f;
                float xB0 = (xyz[(size_t)pB * 3 + 0] - amn0) * sc0 - 1.0f;
                float xB1 = (xyz[(size_t)pB * 3 + 1] - amn1) * sc1 - 1.0f;
                float xB2 = (xyz[(size_t)pB * 3 + 2] - amn2) * sc2 - 1.0f;

                uint32_t a0 = 0u, a1 = 0u;   // k = 2t, 2t+1 for rows g / g+8 (k<8)
                if (tsel == 0) { a0 = pack_h2(xA0, xA1); a1 = pack_h2(xB0, xB1); }
                else if (tsel == 1) { a0 = pack_h2(xA2, 1.0f); a1 = pack_h2(xB2, 1.0f); }

                #pragma unroll
                for (int jj = 0; jj < 4; ++jj) {
                    uint32_t bh[4];
                    ldx4_rows32(bh, u_w0h, lane, 32 * jj);
                    #pragma unroll
                    for (int m = 0; m < 4; ++m) {
                        float* ac = acc[4 * jj + m];
                        mma_f16_k8_zc(ac[0], ac[1], ac[2], ac[3], a0, a1, bh[m]);
                    }
                }
                act_pack0(acc, ahi);
            }

            gemm_layer<16>(acc, ahi, u_w1, lane);
            act_pack(acc, b1s, ahi, lane);
            gemm_layer<16>(acc, ahi, u_w2, lane);
            act_pack(acc, b2s, ahi, lane);
            gemm_layer<8>(acc, ahi, u_w3, lane);

            __syncwarp();
            #pragma unroll
            for (int j = 0; j < 8; ++j) {
                int c = 8 * j + cbase;
                int r0 = hf * 16 + g, r1 = r0 + 8;
                es_w[r0 * ESTR + c]     = acc[j][0] + b3s[c];
                es_w[r0 * ESTR + c + 1] = acc[j][1] + b3s[c + 1];
                es_w[r1 * ESTR + c]     = acc[j][2] + b3s[c];
                es_w[r1 * ESTR + c + 1] = acc[j][3] + b3s[c + 1];
            }
            __syncwarp();
        }

        // ---- epilogue ----
        const int pg = pbase_w + lane;
        if (pg < Npts) {
            // hoist GMEM loads: ~577-cyc latency hidden under the prob tree
            float X = xyz[(size_t)pg * 3 + 0];
            float Y = xyz[(size_t)pg * 3 + 1];
            float Z = xyz[(size_t)pg * 3 + 2];
            float4 qv = *(const float4*)(quats + (size_t)pg * 4);

            const float* xr = es_w + lane * ESTR;
#define XV(i) xr[i]
            unsigned long long TP[8];
            #pragma unroll
            for (int q = 0; q < 8; ++q) TP[q] = 0ull;

            float o1, o2, o3, o4, o5;
            float s0 = sigf(XV(0));
            sm3(XV(1), XV(2), XV(3), o1, o2, o3);
            float P1 = s0 * o1, P2 = s0 * o2, P3 = s0 * o3;
            tacc(TP, tfs_d2, 0, 1.0f - s0);

#define BRP(Pp, pidx, cidx, Pc) { float s_ = sigf(XV(cidx)); Pc = Pp * s_; \
                                  tacc(TP, tfs_d2, pidx, Pp * (1.0f - s_)); }
#define BRL(Pp, pidx, cidx)     { float s_ = sigf(XV(cidx)); \
                                  tacc(TP, tfs_d2, cidx, Pp * s_); \
                                  tacc(TP, tfs_d2, pidx, Pp * (1.0f - s_)); }

            float P4, P5, P6;
            BRP(P1, 1, 4, P4)  BRP(P2, 2, 5, P5)  BRP(P3, 3, 6, P6)
            float P7, P8, P9;
            BRP(P4, 4, 7, P7)  BRP(P5, 5, 8, P8)  BRP(P6, 6, 9, P9)
            BRL(P7, 7, 10)     BRL(P8, 8, 11)

            float P12, P13, P14;
            {
                float gg = sigf(XV(55));
                sm3(XV(12), XV(13), XV(14), o1, o2, o3);
                float a = P9 * gg;
                P12 = a * o1; P13 = a * o2; P14 = a * o3;
                tacc(TP, tfs_d2, 9, P9 * (1.0f - gg));
            }
            float P15, P16, P17;
            BRP(P12, 12, 15, P15) BRP(P13, 13, 16, P16) BRP(P14, 14, 17, P17)
            float P18, P19;
            BRP(P16, 16, 18, P18) BRP(P17, 17, 19, P19)
            float P20, P21;
            BRP(P18, 18, 20, P20) BRP(P19, 19, 21, P21)

            {
                float gg = sigf(XV(56));
                sm3(XV(22), XV(23), XV(24), o1, o2, o3);
                float a = P15 * gg;
                tacc(TP, tfs_d2, 22, a * o1);
                tacc(TP, tfs_d2, 23, a * o2);
                tacc(TP, tfs_d2, 24, a * o3);
                tacc(TP, tfs_d2, 15, P15 * (1.0f - gg));
            }
            float P25, P28, P31, P34, P37;
            {
                float gg = sigf(XV(57));
                sm5(XV(25), XV(28), XV(31), XV(34), XV(37), o1, o2, o3, o4, o5);
                float a = P20 * gg;
                P25 = a * o1; P28 = a * o2; P31 = a * o3; P34 = a * o4; P37 = a * o5;
                tacc(TP, tfs_d2, 20, P20 * (1.0f - gg));
            }
            {
                float Pc;
                BRP(P25, 25, 26, Pc) BRL(Pc, 26, 27)
                BRP(P28, 28, 29, Pc) BRL(Pc, 29, 30)
                BRP(P31, 31, 32, Pc) BRL(Pc, 32, 33)
                BRP(P34, 34, 35, Pc) BRL(Pc, 35, 36)
                BRP(P37, 37, 38, Pc) BRL(Pc, 38, 39)
            }
            float P40, P43, P46, P49, P52;
            {
                float gg = sigf(XV(58));
                sm5(XV(40), XV(43), XV(46), XV(49), XV(52), o1, o2, o3, o4, o5);
                float a = P21 * gg;
                P40 = a * o1; P43 = a * o2; P46 = a * o3; P49 = a * o4; P52 = a * o5;
                tacc(TP, tfs_d2, 21, P21 * (1.0f - gg));
            }
            {
                float Pc;
                BRP(P40, 40, 41, Pc) BRL(Pc, 41, 42)
                BRP(P43, 43, 44, Pc) BRL(Pc, 44, 45)
                BRP(P46, 46, 47, Pc) BRL(Pc, 47, 48)
                BRP(P49, 49, 50, Pc) BRL(Pc, 50, 51)
                BRP(P52, 52, 53, Pc) BRL(Pc, 53, 54)
            }
#undef BRP
#undef BRL
#undef XV

            float T[16];
            #pragma unroll
            for (int q = 0; q < 8; ++q) unpack2(TP[q], T[2 * q], T[2 * q + 1]);

            float xb0 = T[0] * X + T[1] * Y + T[2]  * Z + T[3];
            float xb1 = T[4] * X + T[5] * Y + T[6]  * Z + T[7];
            float xb2 = T[8] * X + T[9] * Y + T[10] * Z + T[11];

            {
                float inv = rsqrtf(qv.x * qv.x + qv.y * qv.y + qv.z * qv.z + qv.w * qv.w);
                qv.x *= inv; qv.y *= inv; qv.z *= inv; qv.w *= inv;
            }
            float r = qv.x, xq = qv.y, yq = qv.z, zq = qv.w;
            float R[3][3];
            R[0][0] = 1.0f - 2.0f * (yq * yq + zq * zq);
            R[0][1] = 2.0f * (xq * yq - r * zq);
            R[0][2] = 2.0f * (xq * zq + r * yq);
            R[1][0] = 2.0f * (xq * yq + r * zq);
            R[1][1] = 1.0f - 2.0f * (xq * xq + zq * zq);
            R[1][2] = 2.0f * (yq * zq - r * xq);
            R[2][0] = 2.0f * (xq * zq - r * yq);
            R[2][1] = 2.0f * (yq * zq + r * xq);
            R[2][2] = 1.0f - 2.0f * (xq * xq + yq * yq);

            float rb[3][3];
            #pragma unroll
            for (int i = 0; i < 3; ++i)
                #pragma unroll
                for (int k = 0; k < 3; ++k)
                    rb[i][k] = T[i * 4 + 0] * R[0][k] + T[i * 4 + 1] * R[1][k] + T[i * 4 + 2] * R[2][k];

            float m00 = rb[0][0], m01 = rb[0][1], m02 = rb[0][2];
            float m10 = rb[1][0], m11 = rb[1][1], m12 = rb[1][2];
            float m20 = rb[2][0], m21 = rb[2][1], m22 = rb[2][2];
            float t0 = 1.0f + m00 + m11 + m22;
            float t1 = 1.0f + m00 - m11 - m22;
            float t2 = 1.0f - m00 + m11 - m22;
            float t3 = 1.0f - m00 - m11 + m22;

            int best = 0; float tb = t0;
            if (t1 > tb) { best = 1; tb = t1; }
            if (t2 > tb) { best = 2; tb = t2; }
            if (t3 > tb) { best = 3; tb = t3; }

            float qa, qb2, qc, qd;
            if (best == 0)      { qa = t0;        qb2 = m21 - m12; qc = m02 - m20; qd = m10 - m01; }
            else if (best == 1) { qa = m21 - m12; qb2 = t1;        qc = m01 + m10; qd = m02 + m20; }
            else if (best == 2) { qa = m02 - m20; qb2 = m01 + m10; qc = t2;        qd = m12 + m21; }
            else                { qa = m10 - m01; qb2 = m02 + m20; qc = m12 + m21; qd = t3;        }
            float scale = 0.5f * rsqrtf(fmaxf(tb, 1e-8f));
            qa *= scale; qb2 *= scale; qc *= scale; qd *= scale;
            float qinv = rsqrtf(qa * qa + qb2 * qb2 + qc * qc + qd * qd);
            qa *= qinv; qb2 *= qinv; qc *= qinv; qd *= qinv;

            const size_t n = (size_t)Npts;
            out[(size_t)pg * 3 + 0] = xb0;
            out[(size_t)pg * 3 + 1] = xb1;
            out[(size_t)pg * 3 + 2] = xb2;
            float* ro = out + 3 * n + (size_t)pg * 9;
            #pragma unroll
            for (int i = 0; i < 3; ++i)
                #pragma unroll
                for (int k = 0; k < 3; ++k) ro[i * 3 + k] = rb[i][k];
            float4* qo = (float4*)(out + 12 * n + (size_t)pg * 4);
            *qo = make_float4(qa, qb2, qc, qd);
            float4* to = (float4*)(out + 16 * n + (size_t)pg * 16);
            to[0] = make_float4(T[0],  T[1],  T[2],  T[3]);
            to[1] = make_float4(T[4],  T[5],  T[6],  T[7]);
            to[2] = make_float4(T[8],  T[9],  T[10], T[11]);
            to[3] = make_float4(T[12], T[13], T[14], T[15]);
        }
        __syncwarp();
    }
}

extern "C" void kernel_launch(void* const* d_in, const int* in_sizes, int n_in,
                              void* d_out, int out_size)
{
    const float* xyz      = (const float*)d_in[0];
    const float* quats    = (const float*)d_in[1];
    const float* tfs      = (const float*)d_in[2];
    const float* aabb_min = (const float*)d_in[3];
    const float* aabb_max = (const float*)d_in[4];
    const float* W0 = (const float*)d_in[5];
    const float* b0 = (const float*)d_in[6];
    const float* W1 = (const float*)d_in[7];
    const float* b1 = (const float*)d_in[8];
    const float* W2 = (const float*)d_in[9];
    const float* b2 = (const float*)d_in[10];
    const float* W3 = (const float*)d_in[11];
    const float* b3 = (const float*)d_in[12];
    float* out = (float*)d_out;

    int Npts = in_sizes[0] / 3;
    int ntiles = (Npts + TILE - 1) / TILE;

    int sms = 0;
    cudaDeviceGetAttribute(&sms, cudaDevAttrMultiProcessorCount, 0);
    if (sms <= 0) sms = 148;
    int grid = (sms < ntiles) ? sms : ntiles;

    prep_kernel<<<64, 256>>>(W0, b0, W1, W2, W3);

    cudaFuncSetAttribute(skin_mma_kernel,
                         cudaFuncAttributeMaxDynamicSharedMemorySize, SMEM_TOTAL);
    skin_mma_kernel<<<grid, 512, SMEM_TOTAL>>>(
        xyz, quats, tfs, aabb_min, aabb_max,
        b1, b2, b3, out, Npts, ntiles);
}

// round 17
// speedup vs baseline: 1.0310x; 1.0310x over previous
#include <cuda_runtime.h>
#include <cuda_fp16.h>
#include <stdint.h>

// SkinningField R17: R16 + tfs T-blend reads moved from SMEM (LDS.128, 75%-busy
// L1TEX) to __constant__ memory (idle constant port). Everything else identical.

#define H    128
#define NB   55
#define TILE 512          // 16 warps x 32 points
#define NWARP 16
#define WSTR 136          // W1/W2/W3 row stride (fp16 elems)
#define W0STR 8           // W0 blob row stride (fp16): 16B rows
#define ESTR 65           // logit staging row stride (floats)

#define OFF_W1  0
#define OFF_W2  34816
#define OFF_W3  69632
#define OFF_W0H 87040                  // 2048 B
#define OFF_B1  (OFF_W0H + 2048)       // 89088
#define OFF_B2  (OFF_B1 + 512)
#define OFF_B3  (OFF_B2 + 512)
#define OFF_ES  (OFF_B3 + 256)         // 90368
#define SMEM_TOTAL (OFF_ES + NWARP * 32 * ESTR * 4)   // 223488

struct __align__(16) WBlob {
    __half w1[128 * WSTR];
    __half w2[128 * WSTR];
    __half w3[64 * WSTR];
    __half w0[128 * W0STR];   // [n][k]: k0..2 = W0 rows, k3 = b0, k4..7 = 0
};
__device__ WBlob g_wt;

__constant__ double2 c_tfs[NB * 4];    // 55 bones x 16 floats as 4x double2

// ---------------- helpers ----------------
__device__ __forceinline__ uint32_t smem_u32(const void* p) {
    uint32_t a;
    asm("{ .reg .u64 t; cvta.to.shared.u64 t, %1; cvt.u32.u64 %0, t; }" : "=r"(a) : "l"(p));
    return a;
}
__device__ __forceinline__ float sigf(float v) {
    return __fdividef(1.0f, 1.0f + __expf(-v));
}
__device__ __forceinline__ void sm3(float a, float b, float c, float& oa, float& ob, float& oc) {
    float m = fmaxf(a, fmaxf(b, c));
    float ea = __expf(a - m), eb = __expf(b - m), ec = __expf(c - m);
    float inv = __fdividef(1.0f, ea + eb + ec);
    oa = ea * inv; ob = eb * inv; oc = ec * inv;
}
__device__ __forceinline__ void sm5(float a, float b, float c, float d, float e,
                                    float& oa, float& ob, float& oc, float& od, float& oe) {
    float m = fmaxf(fmaxf(a, b), fmaxf(fmaxf(c, d), e));
    float ea = __expf(a - m), eb = __expf(b - m), ec = __expf(c - m),
          ed = __expf(d - m), ee = __expf(e - m);
    float inv = __fdividef(1.0f, ea + eb + ec + ed + ee);
    oa = ea * inv; ob = eb * inv; oc = ec * inv; od = ed * inv; oe = ee * inv;
}
__device__ __forceinline__ uint32_t pack_h2(float h0, float h1) {
    uint32_t w;
    asm("cvt.rn.f16x2.f32 %0, %1, %2;" : "=r"(w) : "f"(h1), "f"(h0));
    return w;
}
// exact-form softplus: ln2 * lg2(1 + 2^(x*log2e)); valid for |x| << 88
__device__ __forceinline__ float spf(float x) {
    float e, l;
    asm("ex2.approx.ftz.f32 %0, %1;" : "=f"(e) : "f"(x * 1.4426950408889634f));
    asm("lg2.approx.ftz.f32 %0, %1;" : "=f"(l) : "f"(1.0f + e));
    return 0.6931471805599453f * l;
}

__device__ __forceinline__ unsigned long long fma2(unsigned long long a,
                                                   unsigned long long b,
                                                   unsigned long long c) {
    unsigned long long r;
    asm("fma.rn.f32x2 %0, %1, %2, %3;" : "=l"(r) : "l"(a), "l"(b), "l"(c));
    return r;
}
__device__ __forceinline__ unsigned long long bcast2(float w) {
    unsigned long long r;
    asm("mov.b64 %0, {%1, %1};" : "=l"(r) : "f"(w));
    return r;
}
__device__ __forceinline__ void unpack2(unsigned long long v, float& lo, float& hi) {
    asm("mov.b64 {%0, %1}, %2;" : "=f"(lo), "=f"(hi) : "l"(v));
}

__device__ __forceinline__ void mma_f16(float& d0, float& d1, float& d2, float& d3,
                                        uint32_t a0, uint32_t a1, uint32_t a2, uint32_t a3,
                                        uint32_t b0, uint32_t b1) {
    asm volatile("mma.sync.aligned.m16n8k16.row.col.f32.f16.f16.f32 "
                 "{%0,%1,%2,%3}, {%4,%5,%6,%7}, {%8,%9}, {%0,%1,%2,%3};"
                 : "+f"(d0), "+f"(d1), "+f"(d2), "+f"(d3)
                 : "r"(a0), "r"(a1), "r"(a2), "r"(a3), "r"(b0), "r"(b1));
}
__device__ __forceinline__ void mma_f16_zc(float& d0, float& d1, float& d2, float& d3,
                                           uint32_t a0, uint32_t a1, uint32_t a2, uint32_t a3,
                                           uint32_t b0, uint32_t b1) {
    const float z = 0.0f;
    asm volatile("mma.sync.aligned.m16n8k16.row.col.f32.f16.f16.f32 "
                 "{%0,%1,%2,%3}, {%4,%5,%6,%7}, {%8,%9}, {%10,%11,%12,%13};"
                 : "=f"(d0), "=f"(d1), "=f"(d2), "=f"(d3)
                 : "r"(a0), "r"(a1), "r"(a2), "r"(a3), "r"(b0), "r"(b1),
                   "f"(z), "f"(z), "f"(z), "f"(z));
}
// k8 zero-C MMA: D = A(k8)*B(k8)
__device__ __forceinline__ void mma_f16_k8_zc(float& d0, float& d1, float& d2, float& d3,
                                              uint32_t a0, uint32_t a1, uint32_t b0) {
    const float z = 0.0f;
    asm volatile("mma.sync.aligned.m16n8k8.row.col.f32.f16.f16.f32 "
                 "{%0,%1,%2,%3}, {%4,%5}, {%6}, {%7,%8,%9,%10};"
                 : "=f"(d0), "=f"(d1), "=f"(d2), "=f"(d3)
                 : "r"(a0), "r"(a1), "r"(b0),
                   "f"(z), "f"(z), "f"(z), "f"(z));
}

__device__ __forceinline__ void ldx4s(uint32_t b[4], uint32_t base, int lane,
                                      int n0, int k0, int stride_elem) {
    int grp = lane >> 3, r = lane & 7;
    int row = n0 + r + ((grp >> 1) << 3);
    int col = k0 + ((grp & 1) << 3);
    uint32_t addr = base + (uint32_t)(row * stride_elem + col) * 2u;
    asm volatile("ldmatrix.sync.aligned.m8n8.x4.shared.b16 {%0,%1,%2,%3}, [%4];"
                 : "=r"(b[0]), "=r"(b[1]), "=r"(b[2]), "=r"(b[3]) : "r"(addr));
}
// 32-row x 8-col ldmatrix: rows n0..n0+31 -> 4 n8 k8 frags
__device__ __forceinline__ void ldx4_rows32(uint32_t b[4], uint32_t base, int lane, int n0) {
    uint32_t addr = base + (uint32_t)((n0 + lane) * W0STR) * 2u;
    asm volatile("ldmatrix.sync.aligned.m8n8.x4.shared.b16 {%0,%1,%2,%3}, [%4];"
                 : "=r"(b[0]), "=r"(b[1]), "=r"(b[2]), "=r"(b[3]) : "r"(addr));
}

template <int NC>
__device__ __forceinline__ void gemm_layer(float acc[][4], const uint32_t ahi[8][4],
                                           uint32_t wsm, int lane) {
    #pragma unroll
    for (int kk = 0; kk < 8; ++kk) {
        #pragma unroll
        for (int jj = 0; jj < NC / 2; ++jj) {
            uint32_t bh[4];
            ldx4s(bh, wsm, lane, 16 * jj, 16 * kk, WSTR);
            float* aL = acc[2 * jj];
            float* aR = acc[2 * jj + 1];
            if (kk == 0) {
                mma_f16_zc(aL[0], aL[1], aL[2], aL[3], ahi[kk][0], ahi[kk][1], ahi[kk][2], ahi[kk][3], bh[0], bh[1]);
                mma_f16_zc(aR[0], aR[1], aR[2], aR[3], ahi[kk][0], ahi[kk][1], ahi[kk][2], ahi[kk][3], bh[2], bh[3]);
            } else {
                mma_f16(aL[0], aL[1], aL[2], aL[3], ahi[kk][0], ahi[kk][1], ahi[kk][2], ahi[kk][3], bh[0], bh[1]);
                mma_f16(aR[0], aR[1], aR[2], aR[3], ahi[kk][0], ahi[kk][1], ahi[kk][2], ahi[kk][3], bh[2], bh[3]);
            }
        }
    }
}

__device__ __forceinline__ void act_pack(const float acc[][4], const float* bias_s,
                                         uint32_t ahi[8][4], int lane) {
    const int cbase = 2 * (lane & 3);
    #pragma unroll
    for (int j = 0; j < 16; ++j) {
        int c = 8 * j + cbase;
        float h0 = spf(acc[j][0] + bias_s[c]);
        float h1 = spf(acc[j][1] + bias_s[c + 1]);
        float h2 = spf(acc[j][2] + bias_s[c]);
        float h3 = spf(acc[j][3] + bias_s[c + 1]);
        int kk = j >> 1, half = (j & 1) << 1;
        ahi[kk][half]     = pack_h2(h0, h1);
        ahi[kk][half + 1] = pack_h2(h2, h3);
    }
}
__device__ __forceinline__ void act_pack0(const float acc[][4], uint32_t ahi[8][4]) {
    #pragma unroll
    for (int j = 0; j < 16; ++j) {
        float h0 = spf(acc[j][0]);
        float h1 = spf(acc[j][1]);
        float h2 = spf(acc[j][2]);
        float h3 = spf(acc[j][3]);
        int kk = j >> 1, half = (j & 1) << 1;
        ahi[kk][half]     = pack_h2(h0, h1);
        ahi[kk][half + 1] = pack_h2(h2, h3);
    }
}

// T-blend accumulate: tfs rows from __constant__ (constant port, not LSU)
__device__ __forceinline__ void tacc(unsigned long long TP[8], int b, float w) {
    unsigned long long wpk = bcast2(w);
    #pragma unroll
    for (int i = 0; i < 4; ++i) {
        double2 v = c_tfs[b * 4 + i];
        TP[2 * i]     = fma2(wpk, *(unsigned long long*)&v.x, TP[2 * i]);
        TP[2 * i + 1] = fma2(wpk, *(unsigned long long*)&v.y, TP[2 * i + 1]);
    }
}

// ---------------- prep ----------------
__global__ void prep_kernel(const float* __restrict__ W0, const float* __restrict__ b0,
                            const float* __restrict__ W1, const float* __restrict__ W2,
                            const float* __restrict__ W3) {
    int tid = blockIdx.x * blockDim.x + threadIdx.x;
    int stride = gridDim.x * blockDim.x;
    for (int o = tid; o < 128 * WSTR; o += stride) {
        int n = o / WSTR, k = o % WSTR;
        float f1 = 0.f, f2 = 0.f;
        if (k < 128) { f1 = W1[k * 128 + n]; f2 = W2[k * 128 + n]; }
        g_wt.w1[o] = __float2half_rn(f1);
        g_wt.w2[o] = __float2half_rn(f2);
    }
    for (int o = tid; o < 64 * WSTR; o += stride) {
        int n = o / WSTR, k = o % WSTR;
        float f = (n < 59 && k < 128) ? W3[k * 59 + n] : 0.f;
        g_wt.w3[o] = __float2half_rn(f);
    }
    for (int o = tid; o < 128 * W0STR; o += stride) {
        int n = o / W0STR, k = o % W0STR;
        float f = 0.f;
        if (k < 3)       f = W0[k * 128 + n];
        else if (k == 3) f = b0[n];
        g_wt.w0[o] = __float2half_rn(f);
    }
}

// ---------------- main kernel ----------------
__global__ void __launch_bounds__(512, 1)
skin_mma_kernel(const float* __restrict__ xyz,  const float* __restrict__ quats,
                const float* __restrict__ tfs,  const float* __restrict__ aabb_min,
                const float* __restrict__ aabb_max,
                const float* __restrict__ b1, const float* __restrict__ b2,
                const float* __restrict__ b3,
                float* __restrict__ out, int Npts, int ntiles)
{
    extern __shared__ char smem[];
    const int tid  = threadIdx.x;
    const int wid  = tid >> 5;
    const int lane = tid & 31;

    {
        const uint4* src = (const uint4*)&g_wt;
        uint4* dst = (uint4*)smem;
        for (int i = tid; i < (int)(sizeof(WBlob) / 16); i += 512) dst[i] = src[i];
    }
    float* b1s  = (float*)(smem + OFF_B1);
    float* b2s  = (float*)(smem + OFF_B2);
    float* b3s  = (float*)(smem + OFF_B3);
    if (tid < H) { b1s[tid] = b1[tid]; b2s[tid] = b2[tid]; }
    if (tid < 64) b3s[tid] = (tid < 59) ? b3[tid] : 0.0f;
    __syncthreads();

    const uint32_t u_w1  = smem_u32(smem + OFF_W1);
    const uint32_t u_w2  = smem_u32(smem + OFF_W2);
    const uint32_t u_w3  = smem_u32(smem + OFF_W3);
    const uint32_t u_w0h = smem_u32(smem + OFF_W0H);
    float* es_w = (float*)(smem + OFF_ES) + wid * (32 * ESTR);

    const float amn0 = __ldg(aabb_min + 0), amn1 = __ldg(aabb_min + 1), amn2 = __ldg(aabb_min + 2);
    const float amx0 = __ldg(aabb_max + 0), amx1 = __ldg(aabb_max + 1), amx2 = __ldg(aabb_max + 2);
    const float sc0 = 2.0f / (amx0 - amn0), sc1 = 2.0f / (amx1 - amn1), sc2 = 2.0f / (amx2 - amn2);

    const int g = lane >> 2;
    const int cbase = 2 * (lane & 3);
    const int tsel = lane & 3;
    const int wpar = wid & 1;

    for (int t = blockIdx.x; t < ntiles; t += gridDim.x) {
        const int pbase_w = t * TILE + wid * 32;

        #pragma unroll
        for (int hh = 0; hh < 2; ++hh) {
            const int hf = hh ^ wpar;
            const int base16 = pbase_w + hf * 16;
            uint32_t ahi[8][4];
            float acc[16][4];

            // ---- layer 0 via m16n8k8: A = [xn0,xn1,xn2,1] (K=8, k4..7=0) ----
            {
                int pA = base16 + g;     if (pA >= Npts) pA = Npts - 1;
                int pB = base16 + g + 8; if (pB >= Npts) pB = Npts - 1;
                float xA0 = (xyz[(size_t)pA * 3 + 0] - amn0) * sc0 - 1.0f;
                float xA1 = (xyz[(size_t)pA * 3 + 1] - amn1) * sc1 - 1.0f;
                float xA2 = (xyz[(size_t)pA * 3 + 2] - amn2) * sc2 - 1.0f;
                float xB0 = (xyz[(size_t)pB * 3 + 0] - amn0) * sc0 - 1.0f;
                float xB1 = (xyz[(size_t)pB * 3 + 1] - amn1) * sc1 - 1.0f;
                float xB2 = (xyz[(size_t)pB * 3 + 2] - amn2) * sc2 - 1.0f;

                uint32_t a0 = 0u, a1 = 0u;
                if (tsel == 0) { a0 = pack_h2(xA0, xA1); a1 = pack_h2(xB0, xB1); }
                else if (tsel == 1) { a0 = pack_h2(xA2, 1.0f); a1 = pack_h2(xB2, 1.0f); }

                #pragma unroll
                for (int jj = 0; jj < 4; ++jj) {
                    uint32_t bh[4];
                    ldx4_rows32(bh, u_w0h, lane, 32 * jj);
                    #pragma unroll
                    for (int m = 0; m < 4; ++m) {
                        float* ac = acc[4 * jj + m];
                        mma_f16_k8_zc(ac[0], ac[1], ac[2], ac[3], a0, a1, bh[m]);
                    }
                }
                act_pack0(acc, ahi);
            }

            gemm_layer<16>(acc, ahi, u_w1, lane);
            act_pack(acc, b1s, ahi, lane);
            gemm_layer<16>(acc, ahi, u_w2, lane);
            act_pack(acc, b2s, ahi, lane);
            gemm_layer<8>(acc, ahi, u_w3, lane);

            __syncwarp();
            #pragma unroll
            for (int j = 0; j < 8; ++j) {
                int c = 8 * j + cbase;
                int r0 = hf * 16 + g, r1 = r0 + 8;
                es_w[r0 * ESTR + c]     = acc[j][0] + b3s[c];
                es_w[r0 * ESTR + c + 1] = acc[j][1] + b3s[c + 1];
                es_w[r1 * ESTR + c]     = acc[j][2] + b3s[c];
                es_w[r1 * ESTR + c + 1] = acc[j][3] + b3s[c + 1];
            }
            __syncwarp();
        }

        // ---- epilogue ----
        const int pg = pbase_w + lane;
        if (pg < Npts) {
            float X = xyz[(size_t)pg * 3 + 0];
            float Y = xyz[(size_t)pg * 3 + 1];
            float Z = xyz[(size_t)pg * 3 + 2];
            float4 qv = *(const float4*)(quats + (size_t)pg * 4);

            const float* xr = es_w + lane * ESTR;
#define XV(i) xr[i]
            unsigned long long TP[8];
            #pragma unroll
            for (int q = 0; q < 8; ++q) TP[q] = 0ull;

            float o1, o2, o3, o4, o5;
            float s0 = sigf(XV(0));
            sm3(XV(1), XV(2), XV(3), o1, o2, o3);
            float P1 = s0 * o1, P2 = s0 * o2, P3 = s0 * o3;
            tacc(TP, 0, 1.0f - s0);

#define BRP(Pp, pidx, cidx, Pc) { float s_ = sigf(XV(cidx)); Pc = Pp * s_; \
                                  tacc(TP, pidx, Pp * (1.0f - s_)); }
#define BRL(Pp, pidx, cidx)     { float s_ = sigf(XV(cidx)); \
                                  tacc(TP, cidx, Pp * s_); \
                                  tacc(TP, pidx, Pp * (1.0f - s_)); }

            float P4, P5, P6;
            BRP(P1, 1, 4, P4)  BRP(P2, 2, 5, P5)  BRP(P3, 3, 6, P6)
            float P7, P8, P9;
            BRP(P4, 4, 7, P7)  BRP(P5, 5, 8, P8)  BRP(P6, 6, 9, P9)
            BRL(P7, 7, 10)     BRL(P8, 8, 11)

            float P12, P13, P14;
            {
                float gg = sigf(XV(55));
                sm3(XV(12), XV(13), XV(14), o1, o2, o3);
                float a = P9 * gg;
                P12 = a * o1; P13 = a * o2; P14 = a * o3;
                tacc(TP, 9, P9 * (1.0f - gg));
            }
            float P15, P16, P17;
            BRP(P12, 12, 15, P15) BRP(P13, 13, 16, P16) BRP(P14, 14, 17, P17)
            float P18, P19;
            BRP(P16, 16, 18, P18) BRP(P17, 17, 19, P19)
            float P20, P21;
            BRP(P18, 18, 20, P20) BRP(P19, 19, 21, P21)

            {
                float gg = sigf(XV(56));
                sm3(XV(22), XV(23), XV(24), o1, o2, o3);
                float a = P15 * gg;
                tacc(TP, 22, a * o1);
                tacc(TP, 23, a * o2);
                tacc(TP, 24, a * o3);
                tacc(TP, 15, P15 * (1.0f - gg));
            }
            float P25, P28, P31, P34, P37;
            {
                float gg = sigf(XV(57));
                sm5(XV(25), XV(28), XV(31), XV(34), XV(37), o1, o2, o3, o4, o5);
                float a = P20 * gg;
                P25 = a * o1; P28 = a * o2; P31 = a * o3; P34 = a * o4; P37 = a * o5;
                tacc(TP, 20, P20 * (1.0f - gg));
            }
            {
                float Pc;
                BRP(P25, 25, 26, Pc) BRL(Pc, 26, 27)
                BRP(P28, 28, 29, Pc) BRL(Pc, 29, 30)
                BRP(P31, 31, 32, Pc) BRL(Pc, 32, 33)
                BRP(P34, 34, 35, Pc) BRL(Pc, 35, 36)
                BRP(P37, 37, 38, Pc) BRL(Pc, 38, 39)
            }
            float P40, P43, P46, P49, P52;
            {
                float gg = sigf(XV(58));
                sm5(XV(40), XV(43), XV(46), XV(49), XV(52), o1, o2, o3, o4, o5);
                float a = P21 * gg;
                P40 = a * o1; P43 = a * o2; P46 = a * o3; P49 = a * o4; P52 = a * o5;
                tacc(TP, 21, P21 * (1.0f - gg));
            }
            {
                float Pc;
                BRP(P40, 40, 41, Pc) BRL(Pc, 41, 42)
                BRP(P43, 43, 44, Pc) BRL(Pc, 44, 45)
                BRP(P46, 46, 47, Pc) BRL(Pc, 47, 48)
                BRP(P49, 49, 50, Pc) BRL(Pc, 50, 51)
                BRP(P52, 52, 53, Pc) BRL(Pc, 53, 54)
            }
#undef BRP
#undef BRL
#undef XV

            float T[16];
            #pragma unroll
            for (int q = 0; q < 8; ++q) unpack2(TP[q], T[2 * q], T[2 * q + 1]);

            float xb0 = T[0] * X + T[1] * Y + T[2]  * Z + T[3];
            float xb1 = T[4] * X + T[5] * Y + T[6]  * Z + T[7];
            float xb2 = T[8] * X + T[9] * Y + T[10] * Z + T[11];

            {
                float inv = rsqrtf(qv.x * qv.x + qv.y * qv.y + qv.z * qv.z + qv.w * qv.w);
                qv.x *= inv; qv.y *= inv; qv.z *= inv; qv.w *= inv;
            }
            float r = qv.x, xq = qv.y, yq = qv.z, zq = qv.w;
            float R[3][3];
            R[0][0] = 1.0f - 2.0f * (yq * yq + zq * zq);
            R[0][1] = 2.0f * (xq * yq - r * zq);
            R[0][2] = 2.0f * (xq * zq + r * yq);
            R[1][0] = 2.0f * (xq * yq + r * zq);
            R[1][1] = 1.0f - 2.0f * (xq * xq + zq * zq);
            R[1][2] = 2.0f * (yq * zq - r * xq);
            R[2][0] = 2.0f * (xq * zq - r * yq);
            R[2][1] = 2.0f * (yq * zq + r * xq);
            R[2][2] = 1.0f - 2.0f * (xq * xq + yq * yq);

            float rb[3][3];
            #pragma unroll
            for (int i = 0; i < 3; ++i)
                #pragma unroll
                for (int k = 0; k < 3; ++k)
                    rb[i][k] = T[i * 4 + 0] * R[0][k] + T[i * 4 + 1] * R[1][k] + T[i * 4 + 2] * R[2][k];

            float m00 = rb[0][0], m01 = rb[0][1], m02 = rb[0][2];
            float m10 = rb[1][0], m11 = rb[1][1], m12 = rb[1][2];
            float m20 = rb[2][0], m21 = rb[2][1], m22 = rb[2][2];
            float t0 = 1.0f + m00 + m11 + m22;
            float t1 = 1.0f + m00 - m11 - m22;
            float t2 = 1.0f - m00 + m11 - m22;
            float t3 = 1.0f - m00 - m11 + m22;

            int best = 0; float tb = t0;
            if (t1 > tb) { best = 1; tb = t1; }
            if (t2 > tb) { best = 2; tb = t2; }
            if (t3 > tb) { best = 3; tb = t3; }

            float qa, qb2, qc, qd;
            if (best == 0)      { qa = t0;        qb2 = m21 - m12; qc = m02 - m20; qd = m10 - m01; }
            else if (best == 1) { qa = m21 - m12; qb2 = t1;        qc = m01 + m10; qd = m02 + m20; }
            else if (best == 2) { qa = m02 - m20; qb2 = m01 + m10; qc = t2;        qd = m12 + m21; }
            else                { qa = m10 - m01; qb2 = m02 + m20; qc = m12 + m21; qd = t3;        }
            float scale = 0.5f * rsqrtf(fmaxf(tb, 1e-8f));
            qa *= scale; qb2 *= scale; qc *= scale; qd *= scale;
            float qinv = rsqrtf(qa * qa + qb2 * qb2 + qc * qc + qd * qd);
            qa *= qinv; qb2 *= qinv; qc *= qinv; qd *= qinv;

            const size_t n = (size_t)Npts;
            out[(size_t)pg * 3 + 0] = xb0;
            out[(size_t)pg * 3 + 1] = xb1;
            out[(size_t)pg * 3 + 2] = xb2;
            float* ro = out + 3 * n + (size_t)pg * 9;
            #pragma unroll
            for (int i = 0; i < 3; ++i)
                #pragma unroll
                for (int k = 0; k < 3; ++k) ro[i * 3 + k] = rb[i][k];
            float4* qo = (float4*)(out + 12 * n + (size_t)pg * 4);
            *qo = make_float4(qa, qb2, qc, qd);
            float4* to = (float4*)(out + 16 * n + (size_t)pg * 16);
            to[0] = make_float4(T[0],  T[1],  T[2],  T[3]);
            to[1] = make_float4(T[4],  T[5],  T[6],  T[7]);
            to[2] = make_float4(T[8],  T[9],  T[10], T[11]);
            to[3] = make_float4(T[12], T[13], T[14], T[15]);
        }
        __syncwarp();
    }
}

extern "C" void kernel_launch(void* const* d_in, const int* in_sizes, int n_in,
                              void* d_out, int out_size)
{
    const float* xyz      = (const float*)d_in[0];
    const float* quats    = (const float*)d_in[1];
    const float* tfs      = (const float*)d_in[2];
    const float* aabb_min = (const float*)d_in[3];
    const float* aabb_max = (const float*)d_in[4];
    const float* W0 = (const float*)d_in[5];
    const float* b0 = (const float*)d_in[6];
    const float* W1 = (const float*)d_in[7];
    const float* b1 = (const float*)d_in[8];
    const float* W2 = (const float*)d_in[9];
    const float* b2 = (const float*)d_in[10];
    const float* W3 = (const float*)d_in[11];
    const float* b3 = (const float*)d_in[12];
    float* out = (float*)d_out;

    int Npts = in_sizes[0] / 3;
    int ntiles = (Npts + TILE - 1) / TILE;

    int sms = 0;
    cudaDeviceGetAttribute(&sms, cudaDevAttrMultiProcessorCount, 0);
    if (sms <= 0) sms = 148;
    int grid = (sms < ntiles) ? sms : ntiles;

    // tfs -> constant memory (D2D async, graph-capturable)
    cudaMemcpyToSymbolAsync(c_tfs, tfs, NB * 16 * sizeof(float), 0,
                            cudaMemcpyDeviceToDevice);

    prep_kernel<<<64, 256>>>(W0, b0, W1, W2, W3);

    cudaFuncSetAttribute(skin_mma_kernel,
                         cudaFuncAttributeMaxDynamicSharedMemorySize, SMEM_TOTAL);
    skin_mma_kernel<<<grid, 512, SMEM_TOTAL>>>(
        xyz, quats, tfs, aabb_min, aabb_max,
        b1, b2, b3, out, Npts, ntiles);
}